// round 15
// baseline (speedup 1.0000x reference)
#include <cuda_runtime.h>
#include <cuda_fp16.h>
#include <cuda_bf16.h>
#include <cuda_fp8.h>
#include <cstdint>

// ---------------------------------------------------------------------------
// Problem constants
// ---------------------------------------------------------------------------
constexpr int T_DIM = 8192;
constexpr int H_DIM = 4096;
constexpr float EPS = 1e-6f;

// Scratch (static __device__ arrays; referenced from DEVICE code only —
// host-side use of these symbols passes the host shadow address, which
// GB300's ATS silently accepts -> silent wrong-memory writes).
__device__ float          g_resid[(size_t)T_DIM * H_DIM];    // 128 MB (holds x)
__device__ float          g_ss_part[(size_t)T_DIM * 64];     // 2 MB row-ss partials
__device__ __nv_bfloat16  g_a[(size_t)T_DIM * H_DIM];        // 64 MB
__device__ __nv_bfloat16  g_b[(size_t)H_DIM * H_DIM];        // 32 MB

// ---------------------------------------------------------------------------
// PTX helpers (NO tcgen05 — harness PTX target is base sm_103;
// mbarrier is sm_80-class and compiles fine)
// ---------------------------------------------------------------------------
__device__ __forceinline__ uint32_t smem_u32_of(const void* p) {
    uint32_t a;
    asm("{ .reg .u64 t; cvta.to.shared.u64 t, %1; cvt.u32.u64 %0, t; }"
        : "=r"(a) : "l"(p));
    return a;
}
__device__ __forceinline__ void cp_async16(uint32_t saddr, const void* gaddr) {
    asm volatile("cp.async.cg.shared.global [%0], [%1], 16;" :: "r"(saddr), "l"(gaddr));
}
__device__ __forceinline__ void cp_commit() { asm volatile("cp.async.commit_group;"); }

__device__ __forceinline__ void ldsm_x4(uint32_t* r, uint32_t addr) {
    asm volatile("ldmatrix.sync.aligned.m8n8.x4.shared.b16 {%0,%1,%2,%3}, [%4];"
                 : "=r"(r[0]), "=r"(r[1]), "=r"(r[2]), "=r"(r[3]) : "r"(addr));
}
__device__ __forceinline__ void mma16816(float* d, const uint32_t* a, const uint32_t* b) {
    asm volatile(
        "mma.sync.aligned.m16n8k16.row.col.f32.bf16.bf16.f32 "
        "{%0,%1,%2,%3}, {%4,%5,%6,%7}, {%8,%9}, {%0,%1,%2,%3};"
        : "+f"(d[0]), "+f"(d[1]), "+f"(d[2]), "+f"(d[3])
        : "r"(a[0]), "r"(a[1]), "r"(a[2]), "r"(a[3]), "r"(b[0]), "r"(b[1]));
}

#define MBARRIER_INIT(addr, cnt) \
    asm volatile("mbarrier.init.shared.b64 [%0], %1;" :: "r"(addr), "r"((uint32_t)(cnt)) : "memory")
#define MBARRIER_ARRIVE(addr) \
    asm volatile("mbarrier.arrive.shared.b64 _, [%0];" :: "r"(addr) : "memory")

__device__ __forceinline__ void mbar_wait(uint32_t mbar, uint32_t parity) {
    uint32_t done;
    asm volatile("{\n\t.reg .pred p;\n\t"
                 "mbarrier.try_wait.parity.acquire.cta.shared::cta.b64 p, [%1], %2;\n\t"
                 "selp.b32 %0, 1, 0, p;\n\t}"
                 : "=r"(done) : "r"(mbar), "r"(parity) : "memory");
    if (!done) {
        asm volatile("{\n\t.reg .pred P1;\n\t"
                     "WAIT_LOOP_%=:\n\t"
                     "mbarrier.try_wait.parity.acquire.cta.shared::cta.b64 P1, [%0], %1, 0x989680;\n\t"
                     "@P1 bra.uni WAIT_DONE_%=;\n\t"
                     "bra.uni WAIT_LOOP_%=;\n\t"
                     "WAIT_DONE_%=:\n\t}"
                     :: "r"(mbar), "r"(parity) : "memory");
    }
}

// ---------------------------------------------------------------------------
// Quantization emulation (division-free; exact threshold compares)
// ---------------------------------------------------------------------------
__device__ __forceinline__ float fp8_e4m3_round(float x) {
    __nv_fp8_storage_t r = __nv_cvt_float_to_fp8(x, __NV_SATFINITE, __NV_E4M3);
    __half_raw hr = __nv_cvt_fp8_to_halfraw(r, __NV_E4M3);
    return __half2float(__half(hr));
}

// One 16-element block -> 32B of dequantized bf16 (2x uint4).
// fl(y*gs)/sc >= mid  <=>  fl(y*gs) >= mid*sc   (mid*sc exact: <=3b x <=4b mantissa)
__device__ __forceinline__ void quant_block16(const float* y, float gs, uint4* out) {
    float amax = 0.0f;
#pragma unroll
    for (int j = 0; j < 16; j++) amax = fmaxf(amax, fabsf(y[j]));
    float sc = fminf(__fmul_rn(__fdiv_rn(amax, 6.0f), gs), 448.0f);
    sc = fp8_e4m3_round(sc);
    const float t0 = 0.25f * sc, t1 = 0.75f * sc, t2 = 1.25f * sc, t3 = 1.75f * sc;
    const float t4 = 2.5f * sc, t5 = 3.5f * sc, t6 = 5.0f * sc;
    uint32_t p[8];
#pragma unroll
    for (int jj = 0; jj < 8; jj++) {
        float d[2];
#pragma unroll
        for (int h = 0; h < 2; h++) {
            float yv = y[jj * 2 + h];
            float a = fabsf(__fmul_rn(yv, gs));
            float q = 0.0f;
            q += (a >= t0) ? 0.5f : 0.0f;
            q += (a >= t1) ? 0.5f : 0.0f;
            q += (a >= t2) ? 0.5f : 0.0f;
            q += (a >= t3) ? 0.5f : 0.0f;
            q += (a >= t4) ? 1.0f : 0.0f;
            q += (a >= t5) ? 1.0f : 0.0f;
            q += (a >= t6) ? 2.0f : 0.0f;
            d[h] = copysignf(__fmul_rn(q, sc), yv);   // exact in bf16
        }
        __nv_bfloat162 b2 = __floats2bfloat162_rn(d[0], d[1]);
        p[jj] = *(uint32_t*)&b2;
    }
    out[0] = make_uint4(p[0], p[1], p[2], p[3]);
    out[1] = make_uint4(p[4], p[5], p[6], p[7]);
}

// ---------------------------------------------------------------------------
// Merged auxiliary kernel. Blocks [0, T_DIM) run the activation path;
// blocks [T_DIM, T_DIM+H_DIM) run weight quant for the NEXT layer (safe:
// same-stream ordering means the previous GEMM, the last g_b reader, is done).
// Two concurrent memory-bound roles stack DRAM bandwidth instead of latency.
//   phase 0 activation: x = relu(hs); resid = x; y = rmsnorm(x); quant->g_a
//   phase 1 activation: rstd from g_ss_part; y = rmsnorm(g_resid); quant->g_a
//                       (or emit fp32 y to yout when final_out)
// Arithmetic identical to the previous separate kernels (rel_err-preserving).
// ---------------------------------------------------------------------------
__global__ __launch_bounds__(256)
void aux_kernel(int phase,
                const float* __restrict__ hs,
                const float* __restrict__ norm_w,
                const float* __restrict__ a_gs,
                const float* __restrict__ wq_src,
                const float* __restrict__ wq_gs,
                float* __restrict__ yout, int final_out) {
    const int tid = threadIdx.x;

    if (blockIdx.x >= T_DIM) {
        // ---- weight-quant role ----
        const int row = blockIdx.x - T_DIM;
        const size_t base = (size_t)row * H_DIM;
        float y[16];
        const float4* src = (const float4*)(wq_src + base + tid * 16);
#pragma unroll
        for (int q = 0; q < 4; q++) {
            float4 v = src[q];
            y[q * 4 + 0] = v.x; y[q * 4 + 1] = v.y; y[q * 4 + 2] = v.z; y[q * 4 + 3] = v.w;
        }
        uint4 o[2];
        quant_block16(y, *wq_gs, o);
        uint4* dst = (uint4*)(g_b + base + tid * 16);
        dst[0] = o[0]; dst[1] = o[1];
        return;
    }

    // ---- activation role ----
    __shared__ float warpsum[8];
    __shared__ float s_red;
    const int row = blockIdx.x;
    const size_t base = (size_t)row * H_DIM;

    float x[16];
    float rstd;
    if (phase == 0) {
        // rownorm0: relu + resid store + sum-of-squares
        float ss = 0.0f;
        const float4* s4 = (const float4*)(hs + base + tid * 16);
        float4* r4 = (float4*)(g_resid + base + tid * 16);
#pragma unroll
        for (int q = 0; q < 4; q++) {
            float4 s = s4[q];
            float4 xv = make_float4(fmaxf(s.x, 0.f), fmaxf(s.y, 0.f),
                                    fmaxf(s.z, 0.f), fmaxf(s.w, 0.f));
            r4[q] = xv;
            x[q * 4 + 0] = xv.x; x[q * 4 + 1] = xv.y;
            x[q * 4 + 2] = xv.z; x[q * 4 + 3] = xv.w;
            ss = fmaf(xv.x, xv.x, fmaf(xv.y, xv.y, fmaf(xv.z, xv.z, fmaf(xv.w, xv.w, ss))));
        }
#pragma unroll
        for (int o = 16; o > 0; o >>= 1) ss += __shfl_xor_sync(0xffffffffu, ss, o);
        if ((tid & 31) == 0) warpsum[tid >> 5] = ss;
        __syncthreads();
        if (tid == 0) {
            float t = 0.0f;
#pragma unroll
            for (int i = 0; i < 8; i++) t += warpsum[i];
            s_red = __frsqrt_rn(__fadd_rn(t * (1.0f / (float)H_DIM), EPS));
        }
        __syncthreads();
        rstd = s_red;
    } else {
        // normquant: rstd from precomputed 64 partials (fixed order as before)
        float v = 0.0f;
        if (tid < 64) v = g_ss_part[(size_t)row * 64 + tid];
#pragma unroll
        for (int o = 16; o > 0; o >>= 1) v += __shfl_xor_sync(0xffffffffu, v, o);
        if (tid == 0)  warpsum[0] = v;
        if (tid == 32) warpsum[1] = v;
        __syncthreads();
        const float ss = __fadd_rn(warpsum[0], warpsum[1]);
        rstd = __frsqrt_rn(__fadd_rn(ss * (1.0f / (float)H_DIM), EPS));
        const float4* xs = (const float4*)(g_resid + base + tid * 16);
#pragma unroll
        for (int q = 0; q < 4; q++) {
            float4 xv = xs[q];
            x[q * 4 + 0] = xv.x; x[q * 4 + 1] = xv.y;
            x[q * 4 + 2] = xv.z; x[q * 4 + 3] = xv.w;
        }
    }

    float y[16];
    const float4* nw4 = (const float4*)(norm_w + tid * 16);
#pragma unroll
    for (int q = 0; q < 4; q++) {
        float4 wv = nw4[q];
        y[q * 4 + 0] = __fmul_rn(__fmul_rn(x[q * 4 + 0], rstd), wv.x);
        y[q * 4 + 1] = __fmul_rn(__fmul_rn(x[q * 4 + 1], rstd), wv.y);
        y[q * 4 + 2] = __fmul_rn(__fmul_rn(x[q * 4 + 2], rstd), wv.z);
        y[q * 4 + 3] = __fmul_rn(__fmul_rn(x[q * 4 + 3], rstd), wv.w);
    }
    if (final_out) {
        float4* o4 = (float4*)(yout + base + tid * 16);
#pragma unroll
        for (int q = 0; q < 4; q++)
            o4[q] = make_float4(y[q * 4], y[q * 4 + 1], y[q * 4 + 2], y[q * 4 + 3]);
    } else {
        uint4 o[2];
        quant_block16(y, *a_gs, o);
        uint4* dst = (uint4*)(g_a + base + tid * 16);
        dst[0] = o[0]; dst[1] = o[1];
    }
}

// ---------------------------------------------------------------------------
// bf16 GEMM + fused residual epilogue (UNCHANGED from the R13 winner).
// CTA 128x256, 8 warps of 64x64, BK=32, 4 stages, SROW=80, cross-iteration
// half-0 fragment preload, split-phase mbarrier instead of __syncthreads.
// ---------------------------------------------------------------------------
constexpr int BM = 128, BN = 256, BK = 32, STAGES = 4;
constexpr int SROW_B = 80;
constexpr int A_STAGE_BYTES = BM * SROW_B;                  // 10240
constexpr int B_STAGE_BYTES = BN * SROW_B;                  // 20480
constexpr int STAGE_BYTES = A_STAGE_BYTES + B_STAGE_BYTES;  // 30720
constexpr int GEMM_SMEM = STAGES * STAGE_BYTES;             // 122880

__global__ __launch_bounds__(256, 1)
void gemm_kernel(const float* __restrict__ wg, const float* __restrict__ ag) {
    const __nv_bfloat16* __restrict__ A = g_a;
    const __nv_bfloat16* __restrict__ B = g_b;
    constexpr int K = H_DIM, N = H_DIM;

    extern __shared__ __align__(128) char smem[];
    __shared__ __align__(8) uint64_t s_mbar;
    const uint32_t smem_u32 = smem_u32_of(smem);
    const uint32_t mbar_u32 = smem_u32_of(&s_mbar);

    const int tid = threadIdx.x;
    const int lane = tid & 31, wid = tid >> 5;
    const int blockM = blockIdx.y * BM;
    const int blockN = blockIdx.x * BN;
    const __nv_bfloat16* Abase = A + (size_t)blockM * K;
    const __nv_bfloat16* Bbase = B + (size_t)blockN * K;

    const float alpha = __fdiv_rn(1.0f, __fmul_rn(*wg, *ag));

    const int wm = (wid & 1) * 64;
    const int wn = (wid >> 1) * 64;
    const int g  = lane >> 2;
    const int t4 = lane & 3;

    const int a_row_in = (lane & 15);
    const int a_koff   = (lane >> 4) << 3;
    const int b_nrow   = (lane & 7) + ((lane >> 4) << 3);
    const int b_koff   = ((lane >> 3) & 1) << 3;

    float acc[4][8][4];
#pragma unroll
    for (int mt = 0; mt < 4; mt++)
#pragma unroll
        for (int nt = 0; nt < 8; nt++)
#pragma unroll
            for (int r = 0; r < 4; r++) acc[mt][nt][r] = 0.0f;

    auto load_stage = [&](int slot, int k0) {
        const uint32_t abase = smem_u32 + slot * STAGE_BYTES;
        const uint32_t bbase = abase + A_STAGE_BYTES;
#pragma unroll
        for (int t = 0; t < 2; t++) {
            int chunk = tid + t * 256;
            int r = chunk >> 2, c = chunk & 3;
            cp_async16(abase + r * SROW_B + c * 16, Abase + (size_t)r * K + k0 + c * 8);
        }
#pragma unroll
        for (int t = 0; t < 4; t++) {
            int chunk = tid + t * 256;
            int r = chunk >> 2, c = chunk & 3;
            cp_async16(bbase + r * SROW_B + c * 16, Bbase + (size_t)r * K + k0 + c * 8);
        }
    };

    uint32_t a0[4][4], b0[8][2], a1[4][4], b1[8][2];
    auto load_half = [&](uint32_t af[4][4], uint32_t bf[8][2],
                         uint32_t sa, uint32_t sb, int koff) {
#pragma unroll
        for (int mt = 0; mt < 4; mt++)
            ldsm_x4(af[mt], sa + (wm + mt * 16 + a_row_in) * SROW_B + (koff + a_koff) * 2);
#pragma unroll
        for (int p = 0; p < 4; p++) {
            uint32_t r4[4];
            ldsm_x4(r4, sb + (wn + p * 16 + b_nrow) * SROW_B + (koff + b_koff) * 2);
            bf[p * 2 + 0][0] = r4[0]; bf[p * 2 + 0][1] = r4[1];
            bf[p * 2 + 1][0] = r4[2]; bf[p * 2 + 1][1] = r4[3];
        }
    };
    auto mma_all = [&](uint32_t af[4][4], uint32_t bf[8][2]) {
#pragma unroll
        for (int mt = 0; mt < 4; mt++)
#pragma unroll
            for (int nt = 0; nt < 8; nt++)
                mma16816(acc[mt][nt], af[mt], bf[nt]);
    };

    if (tid == 0) MBARRIER_INIT(mbar_u32, 256);
#pragma unroll
    for (int s = 0; s < STAGES - 1; s++) { load_stage(s, s * BK); cp_commit(); }
    asm volatile("cp.async.wait_group 1;" ::: "memory");
    __syncthreads();
    load_half(a0, b0, smem_u32, smem_u32 + A_STAGE_BYTES, 0);
    MBARRIER_ARRIVE(mbar_u32);

    const int KT = K / BK;   // 128
    for (int i = 0; i < KT; i++) {
        const int slot = i & (STAGES - 1);
        const uint32_t sa = smem_u32 + slot * STAGE_BYTES;
        const uint32_t sb = sa + A_STAGE_BYTES;

        mbar_wait(mbar_u32, (uint32_t)(i & 1));

        if (i + STAGES - 1 < KT)
            load_stage((i + STAGES - 1) & (STAGES - 1), (i + STAGES - 1) * BK);
        cp_commit();

        load_half(a1, b1, sa, sb, 16);
        asm volatile("cp.async.wait_group 1;" ::: "memory");
        MBARRIER_ARRIVE(mbar_u32);

        mma_all(a0, b0);
        if (i + 1 < KT) {
            const uint32_t na = smem_u32 + ((i + 1) & (STAGES - 1)) * STAGE_BYTES;
            load_half(a0, b0, na, na + A_STAGE_BYTES, 0);
        }
        mma_all(a1, b1);
    }

    // --- Fused epilogue: x = fl(z*alpha)+resid -> g_resid; row-ss partials
    const int wnIdx = wid >> 1;
#pragma unroll
    for (int mt = 0; mt < 4; mt++) {
        const int r0 = blockM + wm + mt * 16 + g;
        float* p0 = g_resid + (size_t)r0 * N + blockN + wn;
        float* p1 = p0 + (size_t)8 * N;
        float s0 = 0.0f, s1 = 0.0f;
#pragma unroll
        for (int nt = 0; nt < 8; nt++) {
            const int c = nt * 8 + t4 * 2;
            float2 v0 = *(float2*)(p0 + c);
            float2 v1 = *(float2*)(p1 + c);
            float x00 = __fadd_rn(__fmul_rn(acc[mt][nt][0], alpha), v0.x);
            float x01 = __fadd_rn(__fmul_rn(acc[mt][nt][1], alpha), v0.y);
            float x10 = __fadd_rn(__fmul_rn(acc[mt][nt][2], alpha), v1.x);
            float x11 = __fadd_rn(__fmul_rn(acc[mt][nt][3], alpha), v1.y);
            *(float2*)(p0 + c) = make_float2(x00, x01);
            *(float2*)(p1 + c) = make_float2(x10, x11);
            s0 = fmaf(x00, x00, fmaf(x01, x01, s0));
            s1 = fmaf(x10, x10, fmaf(x11, x11, s1));
        }
        s0 += __shfl_xor_sync(0xffffffffu, s0, 1);
        s0 += __shfl_xor_sync(0xffffffffu, s0, 2);
        s1 += __shfl_xor_sync(0xffffffffu, s1, 1);
        s1 += __shfl_xor_sync(0xffffffffu, s1, 2);
        if (t4 == 0) {
            const int slot2 = blockIdx.x * 4 + wnIdx;    // 0..63
            g_ss_part[(size_t)r0 * 64 + slot2]       = s0;
            g_ss_part[(size_t)(r0 + 8) * 64 + slot2] = s1;
        }
    }
}

// ---------------------------------------------------------------------------
// Host launcher (graph-capturable: kernel launches only)
// ---------------------------------------------------------------------------
extern "C" void kernel_launch(void* const* d_in, const int* in_sizes, int n_in,
                              void* d_out, int out_size) {
    const float *hs = nullptr, *nw = nullptr, *w = nullptr;
    const float *ag = nullptr, *wg = nullptr;
    for (int i = 0; i < n_in; i++) {
        long sz = (long)in_sizes[i];
        if      (sz == (long)T_DIM * H_DIM)      hs = (const float*)d_in[i];
        else if (sz == 4L * H_DIM)               nw = (const float*)d_in[i];
        else if (sz == 3L * H_DIM * H_DIM)       w  = (const float*)d_in[i];
        else if (sz == 3) { if (!ag) ag = (const float*)d_in[i]; else wg = (const float*)d_in[i]; }
    }
    float* out = (float*)d_out;                  // [8192, 4096] fp32

    cudaFuncSetAttribute(gemm_kernel,
                         cudaFuncAttributeMaxDynamicSharedMemorySize, GEMM_SMEM);

    dim3 rblk(256);
    dim3 ggrid(H_DIM / BN, T_DIM / BM);          // (16, 64)

    // Launch A: rownorm0 (8192 blocks) + wquant layer0 (4096 blocks)
    aux_kernel<<<T_DIM + H_DIM, rblk>>>(0, hs, nw, ag + 0,
                                        w, wg + 0, nullptr, 0);
    for (int i = 0; i < 3; i++) {
        gemm_kernel<<<ggrid, rblk, GEMM_SMEM>>>(wg + i, ag + i);
        if (i < 2) {
            // Launch B: normquant(i) + wquant(i+1) concurrently
            aux_kernel<<<T_DIM + H_DIM, rblk>>>(1, nullptr,
                                                nw + (size_t)(i + 1) * H_DIM,
                                                ag + (i + 1),
                                                w + (size_t)(i + 1) * H_DIM * H_DIM,
                                                wg + (i + 1), nullptr, 0);
        } else {
            // Launch C: final normquant only
            aux_kernel<<<T_DIM, rblk>>>(1, nullptr, nw + (size_t)3 * H_DIM,
                                        nullptr, nullptr, nullptr, out, 1);
        }
    }
}

// round 16
// speedup vs baseline: 1.5258x; 1.5258x over previous
#include <cuda_runtime.h>
#include <cuda_fp16.h>
#include <cuda_bf16.h>
#include <cuda_fp8.h>
#include <cstdint>

// ---------------------------------------------------------------------------
// Problem constants
// ---------------------------------------------------------------------------
constexpr int T_DIM = 8192;
constexpr int H_DIM = 4096;
constexpr float EPS = 1e-6f;

// Scratch (static __device__ arrays; referenced from DEVICE code only —
// host-side use of these symbols passes the host shadow address, which
// GB300's ATS silently accepts -> silent wrong-memory writes).
__device__ float          g_resid[(size_t)T_DIM * H_DIM];         // 128 MB (holds x)
__device__ float          g_ss_part[(size_t)T_DIM * 64];          // 2 MB row-ss partials
__device__ __nv_bfloat16  g_a[(size_t)T_DIM * H_DIM];             // 64 MB
__device__ __nv_bfloat16  g_b3[(size_t)3 * H_DIM * H_DIM];        // 96 MB (all 3 layers)

// ---------------------------------------------------------------------------
// PTX helpers (NO tcgen05 — harness PTX target is base sm_103;
// mbarrier is sm_80-class and compiles fine)
// ---------------------------------------------------------------------------
__device__ __forceinline__ uint32_t smem_u32_of(const void* p) {
    uint32_t a;
    asm("{ .reg .u64 t; cvta.to.shared.u64 t, %1; cvt.u32.u64 %0, t; }"
        : "=r"(a) : "l"(p));
    return a;
}
__device__ __forceinline__ void cp_async16(uint32_t saddr, const void* gaddr) {
    asm volatile("cp.async.cg.shared.global [%0], [%1], 16;" :: "r"(saddr), "l"(gaddr));
}
__device__ __forceinline__ void cp_commit() { asm volatile("cp.async.commit_group;"); }

__device__ __forceinline__ void ldsm_x4(uint32_t* r, uint32_t addr) {
    asm volatile("ldmatrix.sync.aligned.m8n8.x4.shared.b16 {%0,%1,%2,%3}, [%4];"
                 : "=r"(r[0]), "=r"(r[1]), "=r"(r[2]), "=r"(r[3]) : "r"(addr));
}
__device__ __forceinline__ void mma16816(float* d, const uint32_t* a, const uint32_t* b) {
    asm volatile(
        "mma.sync.aligned.m16n8k16.row.col.f32.bf16.bf16.f32 "
        "{%0,%1,%2,%3}, {%4,%5,%6,%7}, {%8,%9}, {%0,%1,%2,%3};"
        : "+f"(d[0]), "+f"(d[1]), "+f"(d[2]), "+f"(d[3])
        : "r"(a[0]), "r"(a[1]), "r"(a[2]), "r"(a[3]), "r"(b[0]), "r"(b[1]));
}

#define MBARRIER_INIT(addr, cnt) \
    asm volatile("mbarrier.init.shared.b64 [%0], %1;" :: "r"(addr), "r"((uint32_t)(cnt)) : "memory")
#define MBARRIER_ARRIVE(addr) \
    asm volatile("mbarrier.arrive.shared.b64 _, [%0];" :: "r"(addr) : "memory")

__device__ __forceinline__ void mbar_wait(uint32_t mbar, uint32_t parity) {
    uint32_t done;
    asm volatile("{\n\t.reg .pred p;\n\t"
                 "mbarrier.try_wait.parity.acquire.cta.shared::cta.b64 p, [%1], %2;\n\t"
                 "selp.b32 %0, 1, 0, p;\n\t}"
                 : "=r"(done) : "r"(mbar), "r"(parity) : "memory");
    if (!done) {
        asm volatile("{\n\t.reg .pred P1;\n\t"
                     "WAIT_LOOP_%=:\n\t"
                     "mbarrier.try_wait.parity.acquire.cta.shared::cta.b64 P1, [%0], %1, 0x989680;\n\t"
                     "@P1 bra.uni WAIT_DONE_%=;\n\t"
                     "bra.uni WAIT_LOOP_%=;\n\t"
                     "WAIT_DONE_%=:\n\t}"
                     :: "r"(mbar), "r"(parity) : "memory");
    }
}

// ---------------------------------------------------------------------------
// Quantization emulation (division-free; exact threshold compares)
// ---------------------------------------------------------------------------
__device__ __forceinline__ float fp8_e4m3_round(float x) {
    __nv_fp8_storage_t r = __nv_cvt_float_to_fp8(x, __NV_SATFINITE, __NV_E4M3);
    __half_raw hr = __nv_cvt_fp8_to_halfraw(r, __NV_E4M3);
    return __half2float(__half(hr));
}

// One 16-element block -> 32B of dequantized bf16 (2x uint4).
// fl(y*gs)/sc >= mid  <=>  fl(y*gs) >= mid*sc   (mid*sc exact: <=3b x <=4b mantissa)
__device__ __forceinline__ void quant_block16(const float* y, float gs, uint4* out) {
    float amax = 0.0f;
#pragma unroll
    for (int j = 0; j < 16; j++) amax = fmaxf(amax, fabsf(y[j]));
    float sc = fminf(__fmul_rn(__fdiv_rn(amax, 6.0f), gs), 448.0f);
    sc = fp8_e4m3_round(sc);
    const float t0 = 0.25f * sc, t1 = 0.75f * sc, t2 = 1.25f * sc, t3 = 1.75f * sc;
    const float t4 = 2.5f * sc, t5 = 3.5f * sc, t6 = 5.0f * sc;
    uint32_t p[8];
#pragma unroll
    for (int jj = 0; jj < 8; jj++) {
        float d[2];
#pragma unroll
        for (int h = 0; h < 2; h++) {
            float yv = y[jj * 2 + h];
            float a = fabsf(__fmul_rn(yv, gs));
            float q = 0.0f;
            q += (a >= t0) ? 0.5f : 0.0f;
            q += (a >= t1) ? 0.5f : 0.0f;
            q += (a >= t2) ? 0.5f : 0.0f;
            q += (a >= t3) ? 0.5f : 0.0f;
            q += (a >= t4) ? 1.0f : 0.0f;
            q += (a >= t5) ? 1.0f : 0.0f;
            q += (a >= t6) ? 2.0f : 0.0f;
            d[h] = copysignf(__fmul_rn(q, sc), yv);   // exact in bf16
        }
        __nv_bfloat162 b2 = __floats2bfloat162_rn(d[0], d[1]);
        p[jj] = *(uint32_t*)&b2;
    }
    out[0] = make_uint4(p[0], p[1], p[2], p[3]);
    out[1] = make_uint4(p[4], p[5], p[6], p[7]);
}

// ---------------------------------------------------------------------------
// First layer prologue: x = relu(hs); resid = x; y = rmsnorm(x, w0); quant->g_a
// ---------------------------------------------------------------------------
__global__ __launch_bounds__(256)
void rownorm0_kernel(const float* __restrict__ src,
                     const float* __restrict__ norm_w,
                     const float* __restrict__ a_gs) {
    __shared__ float warpsum[8];
    __shared__ float s_rstd;
    const int row = blockIdx.x;
    const int tid = threadIdx.x;
    const size_t base = (size_t)row * H_DIM;

    float x[16];
    float ss = 0.0f;
    const float4* s4 = (const float4*)(src + base + tid * 16);
    float4* r4 = (float4*)(g_resid + base + tid * 16);
#pragma unroll
    for (int q = 0; q < 4; q++) {
        float4 s = s4[q];
        float4 xv = make_float4(fmaxf(s.x, 0.f), fmaxf(s.y, 0.f),
                                fmaxf(s.z, 0.f), fmaxf(s.w, 0.f));
        r4[q] = xv;
        x[q * 4 + 0] = xv.x; x[q * 4 + 1] = xv.y; x[q * 4 + 2] = xv.z; x[q * 4 + 3] = xv.w;
        ss = fmaf(xv.x, xv.x, fmaf(xv.y, xv.y, fmaf(xv.z, xv.z, fmaf(xv.w, xv.w, ss))));
    }
#pragma unroll
    for (int o = 16; o > 0; o >>= 1) ss += __shfl_xor_sync(0xffffffffu, ss, o);
    if ((tid & 31) == 0) warpsum[tid >> 5] = ss;
    __syncthreads();
    if (tid == 0) {
        float t = 0.0f;
#pragma unroll
        for (int i = 0; i < 8; i++) t += warpsum[i];
        s_rstd = __frsqrt_rn(__fadd_rn(t * (1.0f / (float)H_DIM), EPS));
    }
    __syncthreads();
    const float rstd = s_rstd;

    float y[16];
    const float4* nw4 = (const float4*)(norm_w + tid * 16);
#pragma unroll
    for (int q = 0; q < 4; q++) {
        float4 wv = nw4[q];
        y[q * 4 + 0] = __fmul_rn(__fmul_rn(x[q * 4 + 0], rstd), wv.x);
        y[q * 4 + 1] = __fmul_rn(__fmul_rn(x[q * 4 + 1], rstd), wv.y);
        y[q * 4 + 2] = __fmul_rn(__fmul_rn(x[q * 4 + 2], rstd), wv.z);
        y[q * 4 + 3] = __fmul_rn(__fmul_rn(x[q * 4 + 3], rstd), wv.w);
    }
    uint4 o[2];
    quant_block16(y, *a_gs, o);
    uint4* dst = (uint4*)(g_a + base + tid * 16);
    dst[0] = o[0]; dst[1] = o[1];
}

// ---------------------------------------------------------------------------
// Weight quantization, ALL THREE LAYERS in one launch (12288 blocks).
// One big streaming pass (192 MB read + 96 MB write) instead of three
// latency-bound small launches. Arithmetic identical per block.
// ---------------------------------------------------------------------------
__global__ __launch_bounds__(256)
void wquant_all_kernel(const float* __restrict__ w, const float* __restrict__ wg) {
    const int gid = blockIdx.x;                  // 0 .. 3*H_DIM-1
    const int layer = gid / H_DIM;
    const int tid = threadIdx.x;
    const size_t base = (size_t)gid * H_DIM;     // contiguous across layers
    float y[16];
    const float4* src = (const float4*)(w + base + tid * 16);
#pragma unroll
    for (int q = 0; q < 4; q++) {
        float4 v = src[q];
        y[q * 4 + 0] = v.x; y[q * 4 + 1] = v.y; y[q * 4 + 2] = v.z; y[q * 4 + 3] = v.w;
    }
    uint4 o[2];
    quant_block16(y, wg[layer], o);
    uint4* dst = (uint4*)(g_b3 + base + tid * 16);
    dst[0] = o[0]; dst[1] = o[1];
}

// ---------------------------------------------------------------------------
// bf16 GEMM + fused residual epilogue (R13 winner, unchanged except B source
// indexes g_b3 by layer).
// CTA 128x256, 8 warps of 64x64, BK=32, 4 stages, SROW=80, cross-iteration
// half-0 fragment preload, split-phase mbarrier instead of __syncthreads.
// ---------------------------------------------------------------------------
constexpr int BM = 128, BN = 256, BK = 32, STAGES = 4;
constexpr int SROW_B = 80;
constexpr int A_STAGE_BYTES = BM * SROW_B;                  // 10240
constexpr int B_STAGE_BYTES = BN * SROW_B;                  // 20480
constexpr int STAGE_BYTES = A_STAGE_BYTES + B_STAGE_BYTES;  // 30720
constexpr int GEMM_SMEM = STAGES * STAGE_BYTES;             // 122880

__global__ __launch_bounds__(256, 1)
void gemm_kernel(int layer, const float* __restrict__ wg, const float* __restrict__ ag) {
    const __nv_bfloat16* __restrict__ A = g_a;
    const __nv_bfloat16* __restrict__ B = g_b3 + (size_t)layer * H_DIM * H_DIM;
    constexpr int K = H_DIM, N = H_DIM;

    extern __shared__ __align__(128) char smem[];
    __shared__ __align__(8) uint64_t s_mbar;
    const uint32_t smem_u32 = smem_u32_of(smem);
    const uint32_t mbar_u32 = smem_u32_of(&s_mbar);

    const int tid = threadIdx.x;
    const int lane = tid & 31, wid = tid >> 5;
    const int blockM = blockIdx.y * BM;
    const int blockN = blockIdx.x * BN;
    const __nv_bfloat16* Abase = A + (size_t)blockM * K;
    const __nv_bfloat16* Bbase = B + (size_t)blockN * K;

    const float alpha = __fdiv_rn(1.0f, __fmul_rn(wg[layer], ag[layer]));

    const int wm = (wid & 1) * 64;
    const int wn = (wid >> 1) * 64;
    const int g  = lane >> 2;
    const int t4 = lane & 3;

    const int a_row_in = (lane & 15);
    const int a_koff   = (lane >> 4) << 3;
    const int b_nrow   = (lane & 7) + ((lane >> 4) << 3);
    const int b_koff   = ((lane >> 3) & 1) << 3;

    float acc[4][8][4];
#pragma unroll
    for (int mt = 0; mt < 4; mt++)
#pragma unroll
        for (int nt = 0; nt < 8; nt++)
#pragma unroll
            for (int r = 0; r < 4; r++) acc[mt][nt][r] = 0.0f;

    auto load_stage = [&](int slot, int k0) {
        const uint32_t abase = smem_u32 + slot * STAGE_BYTES;
        const uint32_t bbase = abase + A_STAGE_BYTES;
#pragma unroll
        for (int t = 0; t < 2; t++) {
            int chunk = tid + t * 256;
            int r = chunk >> 2, c = chunk & 3;
            cp_async16(abase + r * SROW_B + c * 16, Abase + (size_t)r * K + k0 + c * 8);
        }
#pragma unroll
        for (int t = 0; t < 4; t++) {
            int chunk = tid + t * 256;
            int r = chunk >> 2, c = chunk & 3;
            cp_async16(bbase + r * SROW_B + c * 16, Bbase + (size_t)r * K + k0 + c * 8);
        }
    };

    uint32_t a0[4][4], b0[8][2], a1[4][4], b1[8][2];
    auto load_half = [&](uint32_t af[4][4], uint32_t bf[8][2],
                         uint32_t sa, uint32_t sb, int koff) {
#pragma unroll
        for (int mt = 0; mt < 4; mt++)
            ldsm_x4(af[mt], sa + (wm + mt * 16 + a_row_in) * SROW_B + (koff + a_koff) * 2);
#pragma unroll
        for (int p = 0; p < 4; p++) {
            uint32_t r4[4];
            ldsm_x4(r4, sb + (wn + p * 16 + b_nrow) * SROW_B + (koff + b_koff) * 2);
            bf[p * 2 + 0][0] = r4[0]; bf[p * 2 + 0][1] = r4[1];
            bf[p * 2 + 1][0] = r4[2]; bf[p * 2 + 1][1] = r4[3];
        }
    };
    auto mma_all = [&](uint32_t af[4][4], uint32_t bf[8][2]) {
#pragma unroll
        for (int mt = 0; mt < 4; mt++)
#pragma unroll
            for (int nt = 0; nt < 8; nt++)
                mma16816(acc[mt][nt], af[mt], bf[nt]);
    };

    if (tid == 0) MBARRIER_INIT(mbar_u32, 256);
#pragma unroll
    for (int s = 0; s < STAGES - 1; s++) { load_stage(s, s * BK); cp_commit(); }
    asm volatile("cp.async.wait_group 1;" ::: "memory");
    __syncthreads();
    load_half(a0, b0, smem_u32, smem_u32 + A_STAGE_BYTES, 0);
    MBARRIER_ARRIVE(mbar_u32);

    const int KT = K / BK;   // 128
    for (int i = 0; i < KT; i++) {
        const int slot = i & (STAGES - 1);
        const uint32_t sa = smem_u32 + slot * STAGE_BYTES;
        const uint32_t sb = sa + A_STAGE_BYTES;

        mbar_wait(mbar_u32, (uint32_t)(i & 1));

        if (i + STAGES - 1 < KT)
            load_stage((i + STAGES - 1) & (STAGES - 1), (i + STAGES - 1) * BK);
        cp_commit();

        load_half(a1, b1, sa, sb, 16);
        asm volatile("cp.async.wait_group 1;" ::: "memory");
        MBARRIER_ARRIVE(mbar_u32);

        mma_all(a0, b0);
        if (i + 1 < KT) {
            const uint32_t na = smem_u32 + ((i + 1) & (STAGES - 1)) * STAGE_BYTES;
            load_half(a0, b0, na, na + A_STAGE_BYTES, 0);
        }
        mma_all(a1, b1);
    }

    // --- Fused epilogue: x = fl(z*alpha)+resid -> g_resid; row-ss partials
    const int wnIdx = wid >> 1;
#pragma unroll
    for (int mt = 0; mt < 4; mt++) {
        const int r0 = blockM + wm + mt * 16 + g;
        float* p0 = g_resid + (size_t)r0 * N + blockN + wn;
        float* p1 = p0 + (size_t)8 * N;
        float s0 = 0.0f, s1 = 0.0f;
#pragma unroll
        for (int nt = 0; nt < 8; nt++) {
            const int c = nt * 8 + t4 * 2;
            float2 v0 = *(float2*)(p0 + c);
            float2 v1 = *(float2*)(p1 + c);
            float x00 = __fadd_rn(__fmul_rn(acc[mt][nt][0], alpha), v0.x);
            float x01 = __fadd_rn(__fmul_rn(acc[mt][nt][1], alpha), v0.y);
            float x10 = __fadd_rn(__fmul_rn(acc[mt][nt][2], alpha), v1.x);
            float x11 = __fadd_rn(__fmul_rn(acc[mt][nt][3], alpha), v1.y);
            *(float2*)(p0 + c) = make_float2(x00, x01);
            *(float2*)(p1 + c) = make_float2(x10, x11);
            s0 = fmaf(x00, x00, fmaf(x01, x01, s0));
            s1 = fmaf(x10, x10, fmaf(x11, x11, s1));
        }
        s0 += __shfl_xor_sync(0xffffffffu, s0, 1);
        s0 += __shfl_xor_sync(0xffffffffu, s0, 2);
        s1 += __shfl_xor_sync(0xffffffffu, s1, 1);
        s1 += __shfl_xor_sync(0xffffffffu, s1, 2);
        if (t4 == 0) {
            const int slot2 = blockIdx.x * 4 + wnIdx;    // 0..63
            g_ss_part[(size_t)r0 * 64 + slot2]       = s0;
            g_ss_part[(size_t)(r0 + 8) * 64 + slot2] = s1;
        }
    }
}

// ---------------------------------------------------------------------------
// Post-GEMM norm: rstd from precomputed partials; normalize + quant (or emit).
// ---------------------------------------------------------------------------
__global__ __launch_bounds__(256)
void normquant_kernel(const float* __restrict__ norm_w,
                      const float* __restrict__ a_gs,
                      float* __restrict__ yout, int final_out) {
    __shared__ float sred[2];
    const int row = blockIdx.x;
    const int tid = threadIdx.x;
    const size_t base = (size_t)row * H_DIM;

    float v = 0.0f;
    if (tid < 64) v = g_ss_part[(size_t)row * 64 + tid];
#pragma unroll
    for (int o = 16; o > 0; o >>= 1) v += __shfl_xor_sync(0xffffffffu, v, o);
    if (tid == 0)  sred[0] = v;
    if (tid == 32) sred[1] = v;
    __syncthreads();
    const float ss = __fadd_rn(sred[0], sred[1]);
    const float rstd = __frsqrt_rn(__fadd_rn(ss * (1.0f / (float)H_DIM), EPS));

    float y[16];
    const float4* xs  = (const float4*)(g_resid + base + tid * 16);
    const float4* nw4 = (const float4*)(norm_w + tid * 16);
#pragma unroll
    for (int q = 0; q < 4; q++) {
        float4 xv = xs[q];
        float4 wv = nw4[q];
        y[q * 4 + 0] = __fmul_rn(__fmul_rn(xv.x, rstd), wv.x);
        y[q * 4 + 1] = __fmul_rn(__fmul_rn(xv.y, rstd), wv.y);
        y[q * 4 + 2] = __fmul_rn(__fmul_rn(xv.z, rstd), wv.z);
        y[q * 4 + 3] = __fmul_rn(__fmul_rn(xv.w, rstd), wv.w);
    }
    if (final_out) {
        float4* o4 = (float4*)(yout + base + tid * 16);
#pragma unroll
        for (int q = 0; q < 4; q++)
            o4[q] = make_float4(y[q * 4], y[q * 4 + 1], y[q * 4 + 2], y[q * 4 + 3]);
    } else {
        uint4 o[2];
        quant_block16(y, *a_gs, o);
        uint4* dst = (uint4*)(g_a + base + tid * 16);
        dst[0] = o[0]; dst[1] = o[1];
    }
}

// ---------------------------------------------------------------------------
// Host launcher (graph-capturable: kernel launches only)
// ---------------------------------------------------------------------------
extern "C" void kernel_launch(void* const* d_in, const int* in_sizes, int n_in,
                              void* d_out, int out_size) {
    const float *hs = nullptr, *nw = nullptr, *w = nullptr;
    const float *ag = nullptr, *wg = nullptr;
    for (int i = 0; i < n_in; i++) {
        long sz = (long)in_sizes[i];
        if      (sz == (long)T_DIM * H_DIM)      hs = (const float*)d_in[i];
        else if (sz == 4L * H_DIM)               nw = (const float*)d_in[i];
        else if (sz == 3L * H_DIM * H_DIM)       w  = (const float*)d_in[i];
        else if (sz == 3) { if (!ag) ag = (const float*)d_in[i]; else wg = (const float*)d_in[i]; }
    }
    float* out = (float*)d_out;                  // [8192, 4096] fp32

    cudaFuncSetAttribute(gemm_kernel,
                         cudaFuncAttributeMaxDynamicSharedMemorySize, GEMM_SMEM);

    dim3 rblk(256);
    dim3 ggrid(H_DIM / BN, T_DIM / BM);          // (16, 64)

    // All 3 layers' weight quant in one streaming launch (overlaps nothing,
    // but replaces three latency-bound launches with one bandwidth-bound one).
    wquant_all_kernel<<<3 * H_DIM, rblk>>>(w, wg);
    rownorm0_kernel<<<T_DIM, rblk>>>(hs, nw, ag + 0);
    for (int i = 0; i < 3; i++) {
        gemm_kernel<<<ggrid, rblk, GEMM_SMEM>>>(i, wg, ag);
        if (i < 2) {
            normquant_kernel<<<T_DIM, rblk>>>(nw + (size_t)(i + 1) * H_DIM,
                                              ag + (i + 1), nullptr, 0);
        } else {
            normquant_kernel<<<T_DIM, rblk>>>(nw + (size_t)3 * H_DIM,
                                              nullptr, out, 1);
        }
    }
}

// round 17
// speedup vs baseline: 1.5419x; 1.0105x over previous
#include <cuda_runtime.h>
#include <cuda_fp16.h>
#include <cuda_bf16.h>
#include <cuda_fp8.h>
#include <cstdint>

// ---------------------------------------------------------------------------
// Problem constants
// ---------------------------------------------------------------------------
constexpr int T_DIM = 8192;
constexpr int H_DIM = 4096;
constexpr float EPS = 1e-6f;

// Scratch (static __device__ arrays; referenced from DEVICE code only —
// host-side use of these symbols passes the host shadow address, which
// GB300's ATS silently accepts -> silent wrong-memory writes).
__device__ float          g_resid[(size_t)T_DIM * H_DIM];         // 128 MB (holds x)
__device__ float          g_ss_part[(size_t)T_DIM * 64];          // 2 MB row-ss partials
__device__ __nv_bfloat16  g_a[(size_t)T_DIM * H_DIM];             // 64 MB
__device__ __nv_bfloat16  g_b3[(size_t)3 * H_DIM * H_DIM];        // 96 MB (all 3 layers)

// ---------------------------------------------------------------------------
// PTX helpers (NO tcgen05 — harness PTX target is base sm_103;
// mbarrier is sm_80-class and compiles fine)
// ---------------------------------------------------------------------------
__device__ __forceinline__ uint32_t smem_u32_of(const void* p) {
    uint32_t a;
    asm("{ .reg .u64 t; cvta.to.shared.u64 t, %1; cvt.u32.u64 %0, t; }"
        : "=r"(a) : "l"(p));
    return a;
}
__device__ __forceinline__ void cp_async16(uint32_t saddr, const void* gaddr) {
    asm volatile("cp.async.cg.shared.global [%0], [%1], 16;" :: "r"(saddr), "l"(gaddr));
}
__device__ __forceinline__ void cp_commit() { asm volatile("cp.async.commit_group;"); }

__device__ __forceinline__ void ldsm_x4(uint32_t* r, uint32_t addr) {
    asm volatile("ldmatrix.sync.aligned.m8n8.x4.shared.b16 {%0,%1,%2,%3}, [%4];"
                 : "=r"(r[0]), "=r"(r[1]), "=r"(r[2]), "=r"(r[3]) : "r"(addr));
}
__device__ __forceinline__ void mma16816(float* d, const uint32_t* a, const uint32_t* b) {
    asm volatile(
        "mma.sync.aligned.m16n8k16.row.col.f32.bf16.bf16.f32 "
        "{%0,%1,%2,%3}, {%4,%5,%6,%7}, {%8,%9}, {%0,%1,%2,%3};"
        : "+f"(d[0]), "+f"(d[1]), "+f"(d[2]), "+f"(d[3])
        : "r"(a[0]), "r"(a[1]), "r"(a[2]), "r"(a[3]), "r"(b[0]), "r"(b[1]));
}

#define MBARRIER_INIT(addr, cnt) \
    asm volatile("mbarrier.init.shared.b64 [%0], %1;" :: "r"(addr), "r"((uint32_t)(cnt)) : "memory")
#define MBARRIER_ARRIVE(addr) \
    asm volatile("mbarrier.arrive.shared.b64 _, [%0];" :: "r"(addr) : "memory")

__device__ __forceinline__ void mbar_wait(uint32_t mbar, uint32_t parity) {
    uint32_t done;
    asm volatile("{\n\t.reg .pred p;\n\t"
                 "mbarrier.try_wait.parity.acquire.cta.shared::cta.b64 p, [%1], %2;\n\t"
                 "selp.b32 %0, 1, 0, p;\n\t}"
                 : "=r"(done) : "r"(mbar), "r"(parity) : "memory");
    if (!done) {
        asm volatile("{\n\t.reg .pred P1;\n\t"
                     "WAIT_LOOP_%=:\n\t"
                     "mbarrier.try_wait.parity.acquire.cta.shared::cta.b64 P1, [%0], %1, 0x989680;\n\t"
                     "@P1 bra.uni WAIT_DONE_%=;\n\t"
                     "bra.uni WAIT_LOOP_%=;\n\t"
                     "WAIT_DONE_%=:\n\t}"
                     :: "r"(mbar), "r"(parity) : "memory");
    }
}

// ---------------------------------------------------------------------------
// Quantization emulation (division-free; exact threshold compares)
// ---------------------------------------------------------------------------
__device__ __forceinline__ float fp8_e4m3_round(float x) {
    __nv_fp8_storage_t r = __nv_cvt_float_to_fp8(x, __NV_SATFINITE, __NV_E4M3);
    __half_raw hr = __nv_cvt_fp8_to_halfraw(r, __NV_E4M3);
    return __half2float(__half(hr));
}

// One 16-element block -> 32B of dequantized bf16 (2x uint4).
// fl(y*gs)/sc >= mid  <=>  fl(y*gs) >= mid*sc   (mid*sc exact: <=3b x <=4b mantissa)
__device__ __forceinline__ void quant_block16(const float* y, float gs, uint4* out) {
    float amax = 0.0f;
#pragma unroll
    for (int j = 0; j < 16; j++) amax = fmaxf(amax, fabsf(y[j]));
    float sc = fminf(__fmul_rn(__fdiv_rn(amax, 6.0f), gs), 448.0f);
    sc = fp8_e4m3_round(sc);
    const float t0 = 0.25f * sc, t1 = 0.75f * sc, t2 = 1.25f * sc, t3 = 1.75f * sc;
    const float t4 = 2.5f * sc, t5 = 3.5f * sc, t6 = 5.0f * sc;
    uint32_t p[8];
#pragma unroll
    for (int jj = 0; jj < 8; jj++) {
        float d[2];
#pragma unroll
        for (int h = 0; h < 2; h++) {
            float yv = y[jj * 2 + h];
            float a = fabsf(__fmul_rn(yv, gs));
            float q = 0.0f;
            q += (a >= t0) ? 0.5f : 0.0f;
            q += (a >= t1) ? 0.5f : 0.0f;
            q += (a >= t2) ? 0.5f : 0.0f;
            q += (a >= t3) ? 0.5f : 0.0f;
            q += (a >= t4) ? 1.0f : 0.0f;
            q += (a >= t5) ? 1.0f : 0.0f;
            q += (a >= t6) ? 2.0f : 0.0f;
            d[h] = copysignf(__fmul_rn(q, sc), yv);   // exact in bf16
        }
        __nv_bfloat162 b2 = __floats2bfloat162_rn(d[0], d[1]);
        p[jj] = *(uint32_t*)&b2;
    }
    out[0] = make_uint4(p[0], p[1], p[2], p[3]);
    out[1] = make_uint4(p[4], p[5], p[6], p[7]);
}

// ---------------------------------------------------------------------------
// Prep kernel: rownorm0 (blocks [0, T_DIM)) + weight quant for ALL 3 layers
// (blocks [T_DIM, T_DIM + 3*H_DIM)). Independent memory-bound roles in one
// launch stack DRAM bandwidth instead of running two partially-idle passes.
// Arithmetic identical to the separate kernels (rel_err-preserving).
// ---------------------------------------------------------------------------
__global__ __launch_bounds__(256)
void prep_kernel(const float* __restrict__ hs,
                 const float* __restrict__ norm_w,
                 const float* __restrict__ a_gs,
                 const float* __restrict__ w,
                 const float* __restrict__ wg) {
    const int tid = threadIdx.x;

    if (blockIdx.x >= T_DIM) {
        // ---- weight-quant role (all three layers, contiguous rows) ----
        const int gid = blockIdx.x - T_DIM;          // 0 .. 3*H_DIM-1
        const int layer = gid / H_DIM;
        const size_t base = (size_t)gid * H_DIM;
        float y[16];
        const float4* src = (const float4*)(w + base + tid * 16);
#pragma unroll
        for (int q = 0; q < 4; q++) {
            float4 v = src[q];
            y[q * 4 + 0] = v.x; y[q * 4 + 1] = v.y; y[q * 4 + 2] = v.z; y[q * 4 + 3] = v.w;
        }
        uint4 o[2];
        quant_block16(y, wg[layer], o);
        uint4* dst = (uint4*)(g_b3 + base + tid * 16);
        dst[0] = o[0]; dst[1] = o[1];
        return;
    }

    // ---- rownorm0 role: x = relu(hs); resid = x; y = rmsnorm(x); quant->g_a
    __shared__ float warpsum[8];
    __shared__ float s_rstd;
    const int row = blockIdx.x;
    const size_t base = (size_t)row * H_DIM;

    float x[16];
    float ss = 0.0f;
    const float4* s4 = (const float4*)(hs + base + tid * 16);
    float4* r4 = (float4*)(g_resid + base + tid * 16);
#pragma unroll
    for (int q = 0; q < 4; q++) {
        float4 s = s4[q];
        float4 xv = make_float4(fmaxf(s.x, 0.f), fmaxf(s.y, 0.f),
                                fmaxf(s.z, 0.f), fmaxf(s.w, 0.f));
        r4[q] = xv;
        x[q * 4 + 0] = xv.x; x[q * 4 + 1] = xv.y; x[q * 4 + 2] = xv.z; x[q * 4 + 3] = xv.w;
        ss = fmaf(xv.x, xv.x, fmaf(xv.y, xv.y, fmaf(xv.z, xv.z, fmaf(xv.w, xv.w, ss))));
    }
#pragma unroll
    for (int o = 16; o > 0; o >>= 1) ss += __shfl_xor_sync(0xffffffffu, ss, o);
    if ((tid & 31) == 0) warpsum[tid >> 5] = ss;
    __syncthreads();
    if (tid == 0) {
        float t = 0.0f;
#pragma unroll
        for (int i = 0; i < 8; i++) t += warpsum[i];
        s_rstd = __frsqrt_rn(__fadd_rn(t * (1.0f / (float)H_DIM), EPS));
    }
    __syncthreads();
    const float rstd = s_rstd;

    float y[16];
    const float4* nw4 = (const float4*)(norm_w + tid * 16);
#pragma unroll
    for (int q = 0; q < 4; q++) {
        float4 wv = nw4[q];
        y[q * 4 + 0] = __fmul_rn(__fmul_rn(x[q * 4 + 0], rstd), wv.x);
        y[q * 4 + 1] = __fmul_rn(__fmul_rn(x[q * 4 + 1], rstd), wv.y);
        y[q * 4 + 2] = __fmul_rn(__fmul_rn(x[q * 4 + 2], rstd), wv.z);
        y[q * 4 + 3] = __fmul_rn(__fmul_rn(x[q * 4 + 3], rstd), wv.w);
    }
    uint4 o[2];
    quant_block16(y, *a_gs, o);
    uint4* dst = (uint4*)(g_a + base + tid * 16);
    dst[0] = o[0]; dst[1] = o[1];
}

// ---------------------------------------------------------------------------
// bf16 GEMM + fused residual epilogue (R13 winner; B indexes g_b3 by layer).
// CTA 128x256, 8 warps of 64x64, BK=32, 4 stages, SROW=80, cross-iteration
// half-0 fragment preload, split-phase mbarrier instead of __syncthreads.
// ---------------------------------------------------------------------------
constexpr int BM = 128, BN = 256, BK = 32, STAGES = 4;
constexpr int SROW_B = 80;
constexpr int A_STAGE_BYTES = BM * SROW_B;                  // 10240
constexpr int B_STAGE_BYTES = BN * SROW_B;                  // 20480
constexpr int STAGE_BYTES = A_STAGE_BYTES + B_STAGE_BYTES;  // 30720
constexpr int GEMM_SMEM = STAGES * STAGE_BYTES;             // 122880

__global__ __launch_bounds__(256, 1)
void gemm_kernel(int layer, const float* __restrict__ wg, const float* __restrict__ ag) {
    const __nv_bfloat16* __restrict__ A = g_a;
    const __nv_bfloat16* __restrict__ B = g_b3 + (size_t)layer * H_DIM * H_DIM;
    constexpr int K = H_DIM, N = H_DIM;

    extern __shared__ __align__(128) char smem[];
    __shared__ __align__(8) uint64_t s_mbar;
    const uint32_t smem_u32 = smem_u32_of(smem);
    const uint32_t mbar_u32 = smem_u32_of(&s_mbar);

    const int tid = threadIdx.x;
    const int lane = tid & 31, wid = tid >> 5;
    const int blockM = blockIdx.y * BM;
    const int blockN = blockIdx.x * BN;
    const __nv_bfloat16* Abase = A + (size_t)blockM * K;
    const __nv_bfloat16* Bbase = B + (size_t)blockN * K;

    const float alpha = __fdiv_rn(1.0f, __fmul_rn(wg[layer], ag[layer]));

    const int wm = (wid & 1) * 64;
    const int wn = (wid >> 1) * 64;
    const int g  = lane >> 2;
    const int t4 = lane & 3;

    const int a_row_in = (lane & 15);
    const int a_koff   = (lane >> 4) << 3;
    const int b_nrow   = (lane & 7) + ((lane >> 4) << 3);
    const int b_koff   = ((lane >> 3) & 1) << 3;

    float acc[4][8][4];
#pragma unroll
    for (int mt = 0; mt < 4; mt++)
#pragma unroll
        for (int nt = 0; nt < 8; nt++)
#pragma unroll
            for (int r = 0; r < 4; r++) acc[mt][nt][r] = 0.0f;

    auto load_stage = [&](int slot, int k0) {
        const uint32_t abase = smem_u32 + slot * STAGE_BYTES;
        const uint32_t bbase = abase + A_STAGE_BYTES;
#pragma unroll
        for (int t = 0; t < 2; t++) {
            int chunk = tid + t * 256;
            int r = chunk >> 2, c = chunk & 3;
            cp_async16(abase + r * SROW_B + c * 16, Abase + (size_t)r * K + k0 + c * 8);
        }
#pragma unroll
        for (int t = 0; t < 4; t++) {
            int chunk = tid + t * 256;
            int r = chunk >> 2, c = chunk & 3;
            cp_async16(bbase + r * SROW_B + c * 16, Bbase + (size_t)r * K + k0 + c * 8);
        }
    };

    uint32_t a0[4][4], b0[8][2], a1[4][4], b1[8][2];
    auto load_half = [&](uint32_t af[4][4], uint32_t bf[8][2],
                         uint32_t sa, uint32_t sb, int koff) {
#pragma unroll
        for (int mt = 0; mt < 4; mt++)
            ldsm_x4(af[mt], sa + (wm + mt * 16 + a_row_in) * SROW_B + (koff + a_koff) * 2);
#pragma unroll
        for (int p = 0; p < 4; p++) {
            uint32_t r4[4];
            ldsm_x4(r4, sb + (wn + p * 16 + b_nrow) * SROW_B + (koff + b_koff) * 2);
            bf[p * 2 + 0][0] = r4[0]; bf[p * 2 + 0][1] = r4[1];
            bf[p * 2 + 1][0] = r4[2]; bf[p * 2 + 1][1] = r4[3];
        }
    };
    auto mma_all = [&](uint32_t af[4][4], uint32_t bf[8][2]) {
#pragma unroll
        for (int mt = 0; mt < 4; mt++)
#pragma unroll
            for (int nt = 0; nt < 8; nt++)
                mma16816(acc[mt][nt], af[mt], bf[nt]);
    };

    if (tid == 0) MBARRIER_INIT(mbar_u32, 256);
#pragma unroll
    for (int s = 0; s < STAGES - 1; s++) { load_stage(s, s * BK); cp_commit(); }
    asm volatile("cp.async.wait_group 1;" ::: "memory");
    __syncthreads();
    load_half(a0, b0, smem_u32, smem_u32 + A_STAGE_BYTES, 0);
    MBARRIER_ARRIVE(mbar_u32);

    const int KT = K / BK;   // 128
    for (int i = 0; i < KT; i++) {
        const int slot = i & (STAGES - 1);
        const uint32_t sa = smem_u32 + slot * STAGE_BYTES;
        const uint32_t sb = sa + A_STAGE_BYTES;

        mbar_wait(mbar_u32, (uint32_t)(i & 1));

        if (i + STAGES - 1 < KT)
            load_stage((i + STAGES - 1) & (STAGES - 1), (i + STAGES - 1) * BK);
        cp_commit();

        load_half(a1, b1, sa, sb, 16);
        asm volatile("cp.async.wait_group 1;" ::: "memory");
        MBARRIER_ARRIVE(mbar_u32);

        mma_all(a0, b0);
        if (i + 1 < KT) {
            const uint32_t na = smem_u32 + ((i + 1) & (STAGES - 1)) * STAGE_BYTES;
            load_half(a0, b0, na, na + A_STAGE_BYTES, 0);
        }
        mma_all(a1, b1);
    }

    // --- Fused epilogue: x = fl(z*alpha)+resid -> g_resid; row-ss partials
    const int wnIdx = wid >> 1;
#pragma unroll
    for (int mt = 0; mt < 4; mt++) {
        const int r0 = blockM + wm + mt * 16 + g;
        float* p0 = g_resid + (size_t)r0 * N + blockN + wn;
        float* p1 = p0 + (size_t)8 * N;
        float s0 = 0.0f, s1 = 0.0f;
#pragma unroll
        for (int nt = 0; nt < 8; nt++) {
            const int c = nt * 8 + t4 * 2;
            float2 v0 = *(float2*)(p0 + c);
            float2 v1 = *(float2*)(p1 + c);
            float x00 = __fadd_rn(__fmul_rn(acc[mt][nt][0], alpha), v0.x);
            float x01 = __fadd_rn(__fmul_rn(acc[mt][nt][1], alpha), v0.y);
            float x10 = __fadd_rn(__fmul_rn(acc[mt][nt][2], alpha), v1.x);
            float x11 = __fadd_rn(__fmul_rn(acc[mt][nt][3], alpha), v1.y);
            *(float2*)(p0 + c) = make_float2(x00, x01);
            *(float2*)(p1 + c) = make_float2(x10, x11);
            s0 = fmaf(x00, x00, fmaf(x01, x01, s0));
            s1 = fmaf(x10, x10, fmaf(x11, x11, s1));
        }
        s0 += __shfl_xor_sync(0xffffffffu, s0, 1);
        s0 += __shfl_xor_sync(0xffffffffu, s0, 2);
        s1 += __shfl_xor_sync(0xffffffffu, s1, 1);
        s1 += __shfl_xor_sync(0xffffffffu, s1, 2);
        if (t4 == 0) {
            const int slot2 = blockIdx.x * 4 + wnIdx;    // 0..63
            g_ss_part[(size_t)r0 * 64 + slot2]       = s0;
            g_ss_part[(size_t)(r0 + 8) * 64 + slot2] = s1;
        }
    }
}

// ---------------------------------------------------------------------------
// Post-GEMM norm: x-row loads issued BEFORE the partial reduction so their
// latency hides under it; arithmetic identical to before.
// ---------------------------------------------------------------------------
__global__ __launch_bounds__(256)
void normquant_kernel(const float* __restrict__ norm_w,
                      const float* __restrict__ a_gs,
                      float* __restrict__ yout, int final_out) {
    __shared__ float sred[2];
    const int row = blockIdx.x;
    const int tid = threadIdx.x;
    const size_t base = (size_t)row * H_DIM;

    // Independent x-row loads first (hide their latency under the reduction)
    float x[16];
    const float4* xs = (const float4*)(g_resid + base + tid * 16);
#pragma unroll
    for (int q = 0; q < 4; q++) {
        float4 xv = xs[q];
        x[q * 4 + 0] = xv.x; x[q * 4 + 1] = xv.y;
        x[q * 4 + 2] = xv.z; x[q * 4 + 3] = xv.w;
    }

    float v = 0.0f;
    if (tid < 64) v = g_ss_part[(size_t)row * 64 + tid];
#pragma unroll
    for (int o = 16; o > 0; o >>= 1) v += __shfl_xor_sync(0xffffffffu, v, o);
    if (tid == 0)  sred[0] = v;
    if (tid == 32) sred[1] = v;
    __syncthreads();
    const float ss = __fadd_rn(sred[0], sred[1]);
    const float rstd = __frsqrt_rn(__fadd_rn(ss * (1.0f / (float)H_DIM), EPS));

    float y[16];
    const float4* nw4 = (const float4*)(norm_w + tid * 16);
#pragma unroll
    for (int q = 0; q < 4; q++) {
        float4 wv = nw4[q];
        y[q * 4 + 0] = __fmul_rn(__fmul_rn(x[q * 4 + 0], rstd), wv.x);
        y[q * 4 + 1] = __fmul_rn(__fmul_rn(x[q * 4 + 1], rstd), wv.y);
        y[q * 4 + 2] = __fmul_rn(__fmul_rn(x[q * 4 + 2], rstd), wv.z);
        y[q * 4 + 3] = __fmul_rn(__fmul_rn(x[q * 4 + 3], rstd), wv.w);
    }
    if (final_out) {
        float4* o4 = (float4*)(yout + base + tid * 16);
#pragma unroll
        for (int q = 0; q < 4; q++)
            o4[q] = make_float4(y[q * 4], y[q * 4 + 1], y[q * 4 + 2], y[q * 4 + 3]);
    } else {
        uint4 o[2];
        quant_block16(y, *a_gs, o);
        uint4* dst = (uint4*)(g_a + base + tid * 16);
        dst[0] = o[0]; dst[1] = o[1];
    }
}

// ---------------------------------------------------------------------------
// Host launcher (graph-capturable: kernel launches only)
// ---------------------------------------------------------------------------
extern "C" void kernel_launch(void* const* d_in, const int* in_sizes, int n_in,
                              void* d_out, int out_size) {
    const float *hs = nullptr, *nw = nullptr, *w = nullptr;
    const float *ag = nullptr, *wg = nullptr;
    for (int i = 0; i < n_in; i++) {
        long sz = (long)in_sizes[i];
        if      (sz == (long)T_DIM * H_DIM)      hs = (const float*)d_in[i];
        else if (sz == 4L * H_DIM)               nw = (const float*)d_in[i];
        else if (sz == 3L * H_DIM * H_DIM)       w  = (const float*)d_in[i];
        else if (sz == 3) { if (!ag) ag = (const float*)d_in[i]; else wg = (const float*)d_in[i]; }
    }
    float* out = (float*)d_out;                  // [8192, 4096] fp32

    cudaFuncSetAttribute(gemm_kernel,
                         cudaFuncAttributeMaxDynamicSharedMemorySize, GEMM_SMEM);

    dim3 rblk(256);
    dim3 ggrid(H_DIM / BN, T_DIM / BM);          // (16, 64)

    // One launch: rownorm0 (8192 blocks) + weight quant for all 3 layers
    // (12288 blocks). Independent roles; DRAM bandwidth stacks.
    prep_kernel<<<T_DIM + 3 * H_DIM, rblk>>>(hs, nw, ag, w, wg);
    for (int i = 0; i < 3; i++) {
        gemm_kernel<<<ggrid, rblk, GEMM_SMEM>>>(i, wg, ag);
        if (i < 2) {
            normquant_kernel<<<T_DIM, rblk>>>(nw + (size_t)(i + 1) * H_DIM,
                                              ag + (i + 1), nullptr, 0);
        } else {
            normquant_kernel<<<T_DIM, rblk>>>(nw + (size_t)3 * H_DIM,
                                              nullptr, out, 1);
        }
    }
}